// round 1
// baseline (speedup 1.0000x reference)
#include <cuda_runtime.h>
#include <math.h>

#define NH   4
#define NN   4096
#define FIN  512
#define FOUT 128
#define LALPHA 0.2f

typedef unsigned long long u64;

// ---------------- scratch (no allocs allowed) ----------------
__device__ float g_ham[NH * FIN * FOUT];   // [h][f][o]
__device__ float g_h[NH * NN * FOUT];      // [h][n][o]
__device__ float g_A[NH * NN];             // exp(fsrc)
__device__ float g_Cv[NH * NN];            // exp(0.2*fsrc)
__device__ float g_Bv[NH * NN];            // exp(fdst)
__device__ float g_Dv[NH * NN];            // exp(0.2*fdst)
__device__ float g_fs[NH * NN];
__device__ float g_fd[NH * NN];

// ---------------- packed f32x2 helpers ----------------
__device__ __forceinline__ u64 pack2(float lo, float hi) {
    u64 r;
    asm("mov.b64 %0, {%1, %2};" : "=l"(r) : "f"(lo), "f"(hi));
    return r;
}
__device__ __forceinline__ void fma2(u64& d, u64 a, u64 b) {
    asm("fma.rn.f32x2 %0, %1, %2, %0;" : "+l"(d) : "l"(a), "l"(b));
}
__device__ __forceinline__ float2 unpack2(u64 v) {
    float lo, hi;
    asm("mov.b64 {%0, %1}, %2;" : "=f"(lo), "=f"(hi) : "l"(v));
    return make_float2(lo, hi);
}

// ---------------- kernel 1: build hamilton ----------------
// hamilton[h][q*128+fi][p*32+oi] = sign(q,p) * W[h][fi][(q^p)*32+oi]
__global__ void build_hamilton_kernel(const float* __restrict__ W) {
    int idx = blockIdx.x * blockDim.x + threadIdx.x;
    if (idx >= NH * FIN * FOUT) return;
    int o = idx & 127;
    int f = (idx >> 7) & 511;
    int h = idx >> 16;             // 128*512 = 65536
    int q = f >> 7, fi = f & 127;
    int p = o >> 5, oi = o & 31;
    int comp = q ^ p;
    const int negmask[4] = {0, 9, 3, 5};   // bitmask over p of negative signs
    float sgn = ((negmask[q] >> p) & 1) ? -1.f : 1.f;
    g_ham[idx] = sgn * W[h * (128 * 128) + fi * 128 + comp * 32 + oi];
}

// ---------------- kernel 2: h = x @ hamilton (per head) ----------------
// grid (NN/64, NH), 128 threads, tile 64x128, K-tile 32
__global__ __launch_bounds__(128) void gemm_h_kernel(const float* __restrict__ x) {
    __shared__ float Xs[64][33];
    __shared__ float Hs[32][132];
    int t = threadIdx.x;
    int h = blockIdx.y;
    int n0 = blockIdx.x * 64;
    int tx = t & 15, ty = t >> 4;
    float acc[8][8];
#pragma unroll
    for (int i = 0; i < 8; i++)
#pragma unroll
        for (int j = 0; j < 8; j++) acc[i][j] = 0.f;
    const float* hamb = g_ham + (size_t)h * (FIN * FOUT);

    for (int f0 = 0; f0 < FIN; f0 += 32) {
        __syncthreads();
#pragma unroll
        for (int i = 0; i < 16; i++) {
            int idx = t + i * 128;
            int r = idx >> 5, c = idx & 31;
            Xs[r][c] = x[(size_t)(n0 + r) * FIN + f0 + c];
        }
#pragma unroll
        for (int i = 0; i < 8; i++) {
            int idx4 = t + i * 128;
            int k = idx4 >> 5, c4 = idx4 & 31;
            *(float4*)&Hs[k][c4 * 4] = *(const float4*)(hamb + (size_t)(f0 + k) * FOUT + c4 * 4);
        }
        __syncthreads();
#pragma unroll
        for (int k = 0; k < 32; k++) {
            float av[8];
#pragma unroll
            for (int i = 0; i < 8; i++) av[i] = Xs[ty * 8 + i][k];
            float4 b0 = *(float4*)&Hs[k][tx * 8];
            float4 b1 = *(float4*)&Hs[k][tx * 8 + 4];
            float bv[8] = {b0.x, b0.y, b0.z, b0.w, b1.x, b1.y, b1.z, b1.w};
#pragma unroll
            for (int i = 0; i < 8; i++)
#pragma unroll
                for (int j = 0; j < 8; j++) acc[i][j] += av[i] * bv[j];
        }
    }
    float* ob = g_h + ((size_t)h * NN + n0) * FOUT;
#pragma unroll
    for (int i = 0; i < 8; i++) {
        int r = ty * 8 + i;
        *(float4*)&ob[(size_t)r * FOUT + tx * 8] =
            make_float4(acc[i][0], acc[i][1], acc[i][2], acc[i][3]);
        *(float4*)&ob[(size_t)r * FOUT + tx * 8 + 4] =
            make_float4(acc[i][4], acc[i][5], acc[i][6], acc[i][7]);
    }
}

// ---------------- kernel 3: f_src/f_dst + exp factors ----------------
// one warp per (h,n)
__global__ void f_exp_kernel(const float* __restrict__ a) {
    int gw = (blockIdx.x * blockDim.x + threadIdx.x) >> 5;
    int lane = threadIdx.x & 31;
    if (gw >= NH * NN) return;
    int h = gw >> 12;   // / NN
    const float* hr = g_h + (size_t)gw * FOUT;
    const float* ah = a + h * 256;
    float s1 = 0.f, s2 = 0.f;
#pragma unroll
    for (int i = lane; i < 128; i += 32) {
        float v = hr[i];
        s1 += v * ah[i];        // a_src
        s2 += v * ah[128 + i];  // a_dst
    }
#pragma unroll
    for (int off = 16; off; off >>= 1) {
        s1 += __shfl_xor_sync(0xffffffffu, s1, off);
        s2 += __shfl_xor_sync(0xffffffffu, s2, off);
    }
    if (lane == 0) {
        g_fs[gw] = s1;
        g_fd[gw] = s2;
        g_A[gw]  = expf(s1);
        g_Cv[gw] = expf(LALPHA * s1);
        g_Bv[gw] = expf(s2);
        g_Dv[gw] = expf(LALPHA * s2);
    }
}

// ---------------- kernel 4: fused masked-softmax attention @ h ----------------
// grid (NN/64, NH), 128 threads. Output tile 64 rows x 128 cols of head h.
// P_nm = adj ? ((fs_n+fd_m>0) ? A_n*B_m : C_n*D_m) : 0   (unnormalized softmax)
// out[n, h*128+o] = elu( (P @ h)[n,o] / rowsum_n )
__global__ __launch_bounds__(128) void attn_kernel(const int* __restrict__ adj,
                                                   float* __restrict__ out) {
    __shared__ float Ps[64][33];
    __shared__ float Vs[32][132];
    __shared__ float stg[96];   // [0:32)=B, [32:64)=D, [64:96)=fd for current m-tile
    __shared__ float rs[64];

    int t = threadIdx.x;
    int h = blockIdx.y;
    int n0 = blockIdx.x * 64;
    int hN = h * NN;

    // P-construction mapping: 2 threads per row, 16 cols each
    int prow = t >> 1;
    int pcb = (t & 1) << 4;
    float An  = g_A[hN + n0 + prow];
    float Cn  = g_Cv[hN + n0 + prow];
    float fsn = g_fs[hN + n0 + prow];

    // FMA mapping: 8x8 per thread (rows ty*8.., cols tx*8..)
    int tx = t & 15, ty = t >> 4;
    u64 acc2[8][4];
#pragma unroll
    for (int i = 0; i < 8; i++)
#pragma unroll
        for (int j = 0; j < 4; j++) acc2[i][j] = 0ull;
    float part = 0.f;

    const float* hbase = g_h + (size_t)hN * FOUT;
    const int* arow = adj + (size_t)(n0 + prow) * NN + pcb;

    for (int m0 = 0; m0 < NN; m0 += 32) {
        __syncthreads();
        if (t < 96) {
            int c = t & 31, w = t >> 5;
            const float* src = (w == 0) ? g_Bv : (w == 1) ? g_Dv : g_fd;
            stg[t] = src[hN + m0 + c];
        }
#pragma unroll
        for (int i = 0; i < 8; i++) {
            int idx4 = t + i * 128;
            int k = idx4 >> 5, c4 = idx4 & 31;
            *(float4*)&Vs[k][c4 * 4] =
                *(const float4*)(hbase + (size_t)(m0 + k) * FOUT + c4 * 4);
        }
        __syncthreads();
        // build P tile (no exp: select precomputed factors)
#pragma unroll
        for (int i = 0; i < 16; i += 4) {
            int4 av = *(const int4*)(arow + m0 + i);
            int am[4] = {av.x, av.y, av.z, av.w};
            int cc = pcb + i;
#pragma unroll
            for (int j = 0; j < 4; j++) {
                int c = cc + j;
                float s = fsn + stg[64 + c];
                float p = (s > 0.f) ? (An * stg[c]) : (Cn * stg[32 + c]);
                p = (am[j] > 0) ? p : 0.f;
                Ps[prow][c] = p;
                part += p;
            }
        }
        __syncthreads();
        // 64x128 += 64x32 * 32x128 with packed f32x2 FMA
#pragma unroll
        for (int k = 0; k < 32; k++) {
            ulonglong2 q0 = *(const ulonglong2*)&Vs[k][tx * 8];
            ulonglong2 q1 = *(const ulonglong2*)&Vs[k][tx * 8 + 4];
            u64 bp[4] = {q0.x, q0.y, q1.x, q1.y};
#pragma unroll
            for (int i = 0; i < 8; i++) {
                float av = Ps[ty * 8 + i][k];
                u64 ap = pack2(av, av);
#pragma unroll
                for (int j = 0; j < 4; j++) fma2(acc2[i][j], ap, bp[j]);
            }
        }
    }

    // row sums (2 partials per row are adjacent lanes)
    part += __shfl_xor_sync(0xffffffffu, part, 1);
    if ((t & 1) == 0) rs[prow] = part;
    __syncthreads();

    // epilogue: normalize, ELU, transpose-store
#pragma unroll
    for (int i = 0; i < 8; i++) {
        int r = ty * 8 + i;
        float inv = 1.f / rs[r];
        float v[8];
#pragma unroll
        for (int j = 0; j < 4; j++) {
            float2 pr = unpack2(acc2[i][j]);
            v[2 * j]     = pr.x * inv;
            v[2 * j + 1] = pr.y * inv;
        }
#pragma unroll
        for (int j = 0; j < 8; j++) v[j] = (v[j] > 0.f) ? v[j] : expm1f(v[j]);
        float* op = out + (size_t)(n0 + r) * (NH * FOUT) + h * FOUT + tx * 8;
        *(float4*)op       = make_float4(v[0], v[1], v[2], v[3]);
        *(float4*)(op + 4) = make_float4(v[4], v[5], v[6], v[7]);
    }
}

// ---------------- launch ----------------
extern "C" void kernel_launch(void* const* d_in, const int* in_sizes, int n_in,
                              void* d_out, int out_size) {
    const float* x  = (const float*)d_in[0];
    const int* adj  = (const int*)d_in[1];
    const float* W  = (const float*)d_in[2];
    const float* a  = (const float*)d_in[3];
    float* out = (float*)d_out;

    build_hamilton_kernel<<<(NH * FIN * FOUT + 255) / 256, 256>>>(W);
    gemm_h_kernel<<<dim3(NN / 64, NH), 128>>>(x);
    f_exp_kernel<<<(NH * NN) / 8, 256>>>(a);
    attn_kernel<<<dim3(NN / 64, NH), 128>>>(adj, out);
}

// round 3
// speedup vs baseline: 2.1088x; 2.1088x over previous
#include <cuda_runtime.h>
#include <cuda_bf16.h>
#include <math.h>
#include <stdint.h>

#define NH   4
#define NN   4096
#define FIN  512
#define FOUT 128
#define LALPHA 0.2f
#define CH   64
#define NC   (NN / CH)

typedef unsigned long long u64;
typedef unsigned int u32;

// ---------------- scratch ----------------
__device__ float g_ham[NH * FIN * FOUT];
__device__ float g_h[NH * NN * FOUT];
__device__ float g_A[NH * NN];
__device__ float g_Cv[NH * NN];
__device__ float g_fs[NH * NN];
__device__ float4 g_cp[NH * NN];                 // (fd, exp(fd), exp(0.2fd), 0)
__device__ u32 g_adjb[NN * (NN / 32)];
__device__ __nv_bfloat16 g_hTh[NH * FOUT * NN];  // [h][o][m] hi
__device__ __nv_bfloat16 g_hTl[NH * FOUT * NN];  // [h][o][m] lo

// ---------------- helpers ----------------
__device__ __forceinline__ u64 pack2(float lo, float hi) {
    u64 r; asm("mov.b64 %0, {%1, %2};" : "=l"(r) : "f"(lo), "f"(hi)); return r;
}
__device__ __forceinline__ void fma2(u64& d, u64 a, u64 b) {
    asm("fma.rn.f32x2 %0, %1, %2, %0;" : "+l"(d) : "l"(a), "l"(b));
}
__device__ __forceinline__ float2 unpack2(u64 v) {
    float lo, hi; asm("mov.b64 {%0, %1}, %2;" : "=f"(lo), "=f"(hi) : "l"(v));
    return make_float2(lo, hi);
}
__device__ __forceinline__ u32 smem_u32(const void* p) {
    u32 a; asm("{ .reg .u64 t; cvta.to.shared.u64 t, %1; cvt.u32.u64 %0, t; }" : "=r"(a) : "l"(p));
    return a;
}
#define SW128(x) ((x) ^ (((x) >> 3) & 0x70))

#define LDM4(d, addr) \
    asm volatile("ldmatrix.sync.aligned.m8n8.x4.shared.b16 {%0,%1,%2,%3}, [%4];" \
        : "=r"((d)[0]), "=r"((d)[1]), "=r"((d)[2]), "=r"((d)[3]) : "r"(addr))

#define MMA_BF16(c, a, b0, b1) \
    asm volatile("mma.sync.aligned.m16n8k16.row.col.f32.bf16.bf16.f32 " \
        "{%0,%1,%2,%3},{%4,%5,%6,%7},{%8,%9},{%0,%1,%2,%3};" \
        : "+f"((c)[0]), "+f"((c)[1]), "+f"((c)[2]), "+f"((c)[3]) \
        : "r"((a)[0]), "r"((a)[1]), "r"((a)[2]), "r"((a)[3]), "r"(b0), "r"(b1))

#define CPASYNC16(dst, src) \
    asm volatile("cp.async.cg.shared.global [%0], [%1], 16;" :: "r"(dst), "l"(src))

// ---------------- kernel 1: hamilton ----------------
__global__ void build_hamilton_kernel(const float* __restrict__ W) {
    int idx = blockIdx.x * blockDim.x + threadIdx.x;
    if (idx >= NH * FIN * FOUT) return;
    int o = idx & 127, f = (idx >> 7) & 511, h = idx >> 16;
    int q = f >> 7, fi = f & 127, p = o >> 5, oi = o & 31;
    const int negmask[4] = {0, 9, 3, 5};
    float sgn = ((negmask[q] >> p) & 1) ? -1.f : 1.f;
    g_ham[idx] = sgn * W[h * (128 * 128) + fi * 128 + (q ^ p) * 32 + oi];
}

// ---------------- kernel 2: h = x @ hamilton ----------------
__global__ __launch_bounds__(128) void gemm_h_kernel(const float* __restrict__ x) {
    __shared__ float Xs[64][33];
    __shared__ float Hs[32][132];
    int t = threadIdx.x;
    int h = blockIdx.y, n0 = blockIdx.x * 64;
    int tx = t & 15, ty = t >> 4;
    u64 acc2[8][4];
#pragma unroll
    for (int i = 0; i < 8; i++)
#pragma unroll
        for (int j = 0; j < 4; j++) acc2[i][j] = 0ull;
    const float* hamb = g_ham + (size_t)h * (FIN * FOUT);

    for (int f0 = 0; f0 < FIN; f0 += 32) {
        __syncthreads();
#pragma unroll
        for (int i = 0; i < 16; i++) {
            int idx = t + i * 128;
            int r = idx >> 5, c = idx & 31;
            Xs[r][c] = x[(size_t)(n0 + r) * FIN + f0 + c];
        }
#pragma unroll
        for (int i = 0; i < 8; i++) {
            int idx4 = t + i * 128;
            int k = idx4 >> 5, c4 = idx4 & 31;
            *(float4*)&Hs[k][c4 * 4] = *(const float4*)(hamb + (size_t)(f0 + k) * FOUT + c4 * 4);
        }
        __syncthreads();
#pragma unroll
        for (int k = 0; k < 32; k++) {
            ulonglong2 q0 = *(const ulonglong2*)&Hs[k][tx * 8];
            ulonglong2 q1 = *(const ulonglong2*)&Hs[k][tx * 8 + 4];
            u64 bp[4] = {q0.x, q0.y, q1.x, q1.y};
#pragma unroll
            for (int i = 0; i < 8; i++) {
                float av = Xs[ty * 8 + i][k];
                u64 ap = pack2(av, av);
#pragma unroll
                for (int j = 0; j < 4; j++) fma2(acc2[i][j], ap, bp[j]);
            }
        }
    }
    float* ob = g_h + ((size_t)h * NN + n0) * FOUT;
#pragma unroll
    for (int i = 0; i < 8; i++) {
        int r = ty * 8 + i;
        float2 v0 = unpack2(acc2[i][0]), v1 = unpack2(acc2[i][1]);
        float2 v2 = unpack2(acc2[i][2]), v3 = unpack2(acc2[i][3]);
        *(float4*)&ob[(size_t)r * FOUT + tx * 8]     = make_float4(v0.x, v0.y, v1.x, v1.y);
        *(float4*)&ob[(size_t)r * FOUT + tx * 8 + 4] = make_float4(v2.x, v2.y, v3.x, v3.y);
    }
}

// ---------------- kernel 3: f + exp factors ----------------
__global__ void f_exp_kernel(const float* __restrict__ a) {
    int gw = (blockIdx.x * blockDim.x + threadIdx.x) >> 5;
    int lane = threadIdx.x & 31;
    if (gw >= NH * NN) return;
    int h = gw >> 12;
    const float* hr = g_h + (size_t)gw * FOUT;
    const float* ah = a + h * 256;
    float s1 = 0.f, s2 = 0.f;
#pragma unroll
    for (int i = lane; i < 128; i += 32) {
        float v = hr[i];
        s1 += v * ah[i];
        s2 += v * ah[128 + i];
    }
#pragma unroll
    for (int off = 16; off; off >>= 1) {
        s1 += __shfl_xor_sync(0xffffffffu, s1, off);
        s2 += __shfl_xor_sync(0xffffffffu, s2, off);
    }
    if (lane == 0) {
        g_fs[gw] = s1;
        g_A[gw] = expf(s1);
        g_Cv[gw] = expf(LALPHA * s1);
        g_cp[gw] = make_float4(s2, expf(s2), expf(LALPHA * s2), 0.f);
    }
}

// ---------------- kernel 3b: pack adj bits ----------------
__global__ void pack_adj_kernel(const int* __restrict__ adj) {
    int idx = blockIdx.x * blockDim.x + threadIdx.x;
    if (idx >= NN * (NN / 32)) return;
    int n = idx >> 7, w = idx & 127;
    const int4* p = (const int4*)(adj + (size_t)n * NN + w * 32);
    u32 word = 0;
#pragma unroll
    for (int i = 0; i < 8; i++) {
        int4 v = p[i];
        word |= (u32)(v.x > 0) << (i * 4);
        word |= (u32)(v.y > 0) << (i * 4 + 1);
        word |= (u32)(v.z > 0) << (i * 4 + 2);
        word |= (u32)(v.w > 0) << (i * 4 + 3);
    }
    g_adjb[idx] = word;
}

// ---------------- kernel 3c: hT hi/lo bf16 ----------------
__global__ void transpose_split_kernel() {
    __shared__ float st[32][33];
    int h = blockIdx.z;
    int n0 = blockIdx.x * 32, o0 = blockIdx.y * 32;
    int tx = threadIdx.x, ty = threadIdx.y;
#pragma unroll
    for (int yy = 0; yy < 4; yy++) {
        int nl = ty * 4 + yy;
        st[nl][tx] = g_h[((size_t)h * NN + n0 + nl) * FOUT + o0 + tx];
    }
    __syncthreads();
#pragma unroll
    for (int yy = 0; yy < 4; yy++) {
        int ol = ty * 4 + yy;
        float v = st[tx][ol];
        __nv_bfloat16 hi = __float2bfloat16(v);
        __nv_bfloat16 lo = __float2bfloat16(v - __bfloat162float(hi));
        size_t off = ((size_t)h * FOUT + o0 + ol) * NN + n0 + tx;
        g_hTh[off] = hi;
        g_hTl[off] = lo;
    }
}

// ---------------- kernel 4: HMMA attention ----------------
// grid (32, 4), 256 threads. Tile M=128(n) x N=128(o), K chunks of 64(m).
// SMEM layout (dynamic):
#define SM_RS    0                       // 128 floats
#define SM_PRM   512                     // 2 * 64 float4 = 2048
#define SM_TILES 4096
#define STAGE_SZ 65536                   // Ph 16K | Pl 16K | Bh 16K | Bl 16K
#define SM_TOTAL (SM_TILES + 2 * STAGE_SZ)

__device__ __forceinline__ void build_P(char* Ph, char* Pl, const float4* prm,
                                        int r, int cb, u32 aw,
                                        float An, float Cn, float fsn, float& rsum) {
#pragma unroll
    for (int jj = 0; jj < 32; jj += 8) {
        u32 hp[4], lp[4];
#pragma unroll
        for (int q = 0; q < 4; q++) {
            float p[2];
#pragma unroll
            for (int e = 0; e < 2; e++) {
                int j = jj + q * 2 + e;
                float4 pr = prm[cb + j];
                float s1 = fsn + pr.x;
                float v = (s1 > 0.f) ? (An * pr.y) : (Cn * pr.z);
                p[e] = ((aw >> j) & 1) ? v : 0.f;
                rsum += p[e];
            }
            u32 hh;
            asm("cvt.rn.bf16x2.f32 %0, %1, %2;" : "=r"(hh) : "f"(p[1]), "f"(p[0]));
            hp[q] = hh;
            float l0 = p[0] - __uint_as_float(hh << 16);
            float l1 = p[1] - __uint_as_float(hh & 0xffff0000u);
            asm("cvt.rn.bf16x2.f32 %0, %1, %2;" : "=r"(lp[q]) : "f"(l1), "f"(l0));
        }
        u32 sw = SW128((u32)(r * 128 + (cb + jj) * 2));
        *(uint4*)(Ph + sw) = make_uint4(hp[0], hp[1], hp[2], hp[3]);
        *(uint4*)(Pl + sw) = make_uint4(lp[0], lp[1], lp[2], lp[3]);
    }
}

__global__ __launch_bounds__(256, 1) void attn_mma_kernel(float* __restrict__ out) {
    extern __shared__ char smem[];
    u32 sb = smem_u32(smem);
    float* rs = (float*)(smem + SM_RS);
    float4* prm_all = (float4*)(smem + SM_PRM);

    int t = threadIdx.x;
    int wid = t >> 5, L = t & 31;
    int h = blockIdx.y, n0 = blockIdx.x * 128, hN = h * NN;

    // P-build mapping
    int r = t >> 1, chalf = t & 1, cb = chalf * 32;
    float An = g_A[hN + n0 + r], Cn = g_Cv[hN + n0 + r], fsn = g_fs[hN + n0 + r];
    const u32* adjrow = g_adjb + (size_t)(n0 + r) * (NN / 32) + chalf;
    float rsum = 0.f;

    // MMA warp mapping: 4 warp-rows x 2 warp-cols
    int wr = wid & 3, wc = wid >> 2;
    float acc[2][8][4];
#pragma unroll
    for (int mt = 0; mt < 2; mt++)
#pragma unroll
        for (int n8 = 0; n8 < 8; n8++)
#pragma unroll
            for (int e = 0; e < 4; e++) acc[mt][n8][e] = 0.f;

    const __nv_bfloat16* hTh = g_hTh + (size_t)h * FOUT * NN;
    const __nv_bfloat16* hTl = g_hTl + (size_t)h * FOUT * NN;
    const float4* gcp = g_cp + hN;

    u32 xorx = (u32)((L & 7) << 4);

    // ---- prologue: B(0) loads + params(0) + build P(0) ----
    {
        u32 bh0 = sb + SM_TILES + 32768, bl0 = sb + SM_TILES + 49152;
#pragma unroll
        for (int i = 0; i < 4; i++) {
            int idx = t + i * 256;
            int o = idx >> 3, seg = idx & 7;
            u32 sw = SW128((u32)(o * 128 + seg * 16));
            CPASYNC16(bh0 + sw, hTh + (size_t)o * NN + seg * 8);
            CPASYNC16(bl0 + sw, hTl + (size_t)o * NN + seg * 8);
        }
        asm volatile("cp.async.commit_group;" ::: "memory");
        if (t < 64) prm_all[t] = gcp[t];
        __syncthreads();
        build_P(smem + SM_TILES, smem + SM_TILES + 16384, prm_all,
                r, cb, adjrow[0], An, Cn, fsn, rsum);
    }

    for (int c = 0; c < NC; c++) {
        int s = c & 1;
        int sn = s ^ 1;
        u32 stage  = sb + SM_TILES + s * STAGE_SZ;
        char* stgc = smem + SM_TILES + sn * STAGE_SZ;
        bool more = (c + 1 < NC);
        int m0n = (c + 1) * CH;

        __syncthreads();   // prev MMA done everywhere; P(s) stores visible

        if (more) {
            u32 bhn = sb + SM_TILES + sn * STAGE_SZ + 32768;
            u32 bln = bhn + 16384;
#pragma unroll
            for (int i = 0; i < 4; i++) {
                int idx = t + i * 256;
                int o = idx >> 3, seg = idx & 7;
                u32 sw = SW128((u32)(o * 128 + seg * 16));
                CPASYNC16(bhn + sw, hTh + (size_t)o * NN + m0n + seg * 8);
                CPASYNC16(bln + sw, hTl + (size_t)o * NN + m0n + seg * 8);
            }
            asm volatile("cp.async.commit_group;" ::: "memory");
            if (t < 64) prm_all[sn * 64 + t] = gcp[m0n + t];
        }
        if (more) asm volatile("cp.async.wait_group 1;" ::: "memory");
        else      asm volatile("cp.async.wait_group 0;" ::: "memory");
        __syncthreads();   // B(s) + params(sn) visible

        // ---- MMA over stage s ----
        {
            u32 aPh = stage, aPl = stage + 16384;
            u32 bBh = stage + 32768, bBl = stage + 49152;
            u32 aRow = (u32)((wr * 32 + (L & 15)) * 128);
            u32 aHalf = (u32)((L >> 4) * 16);
            u32 bRow = (u32)((wc * 64 + ((L >> 4) & 1) * 8 + (L & 7)) * 128);
            u32 bHalf = (u32)(((L >> 3) & 1) * 16);
#pragma unroll
            for (int kt = 0; kt < 4; kt++) {
                u32 aCol = ((u32)(kt * 32) + aHalf) ^ xorx;
                u32 bCol = ((u32)(kt * 32) + bHalf) ^ xorx;
                u32 ah[2][4], al[2][4];
#pragma unroll
                for (int mt = 0; mt < 2; mt++) {
                    u32 ra = aRow + (u32)(mt * 2048) + aCol;
                    LDM4(ah[mt], aPh + ra);
                    LDM4(al[mt], aPl + ra);
                }
#pragma unroll
                for (int ng = 0; ng < 4; ng++) {
                    u32 rb = bRow + (u32)(ng * 2048) + bCol;
                    u32 bh[4], bl[4];
                    LDM4(bh, bBh + rb);
                    LDM4(bl, bBl + rb);
#pragma unroll
                    for (int mt = 0; mt < 2; mt++) {
                        MMA_BF16(acc[mt][2 * ng], ah[mt], bh[0], bh[1]);
                        MMA_BF16(acc[mt][2 * ng], ah[mt], bl[0], bl[1]);
                        MMA_BF16(acc[mt][2 * ng], al[mt], bh[0], bh[1]);
                        MMA_BF16(acc[mt][2 * ng + 1], ah[mt], bh[2], bh[3]);
                        MMA_BF16(acc[mt][2 * ng + 1], ah[mt], bl[2], bl[3]);
                        MMA_BF16(acc[mt][2 * ng + 1], al[mt], bh[2], bh[3]);
                    }
                }
            }
        }

        // ---- build P(c+1) into stage sn ----
        if (more)
            build_P(stgc, stgc + 16384, prm_all + sn * 64,
                    r, cb, adjrow[m0n >> 5], An, Cn, fsn, rsum);
    }

    // ---- row sums ----
    rsum += __shfl_xor_sync(0xffffffffu, rsum, 1);
    if ((t & 1) == 0) rs[r] = rsum;
    __syncthreads();

    // ---- epilogue: normalize + ELU + store ----
    int gid = L >> 2, tid = L & 3;
#pragma unroll
    for (int mt = 0; mt < 2; mt++) {
#pragma unroll
        for (int half = 0; half < 2; half++) {
            int rt = wr * 32 + mt * 16 + half * 8 + gid;
            float inv = 1.f / rs[rt];
            float* op = out + (size_t)(n0 + rt) * (NH * FOUT) + h * FOUT + wc * 64 + tid * 2;
#pragma unroll
            for (int n8 = 0; n8 < 8; n8++) {
                float v0 = acc[mt][n8][half * 2] * inv;
                float v1 = acc[mt][n8][half * 2 + 1] * inv;
                v0 = (v0 > 0.f) ? v0 : expm1f(v0);
                v1 = (v1 > 0.f) ? v1 : expm1f(v1);
                *(float2*)(op + n8 * 8) = make_float2(v0, v1);
            }
        }
    }
}

// ---------------- launch ----------------
extern "C" void kernel_launch(void* const* d_in, const int* in_sizes, int n_in,
                              void* d_out, int out_size) {
    const float* x  = (const float*)d_in[0];
    const int* adj  = (const int*)d_in[1];
    const float* W  = (const float*)d_in[2];
    const float* a  = (const float*)d_in[3];
    float* out = (float*)d_out;

    cudaFuncSetAttribute(attn_mma_kernel, cudaFuncAttributeMaxDynamicSharedMemorySize, SM_TOTAL);

    build_hamilton_kernel<<<(NH * FIN * FOUT + 255) / 256, 256>>>(W);
    gemm_h_kernel<<<dim3(NN / 64, NH), 128>>>(x);
    f_exp_kernel<<<(NH * NN) / 8, 256>>>(a);
    pack_adj_kernel<<<(NN * (NN / 32)) / 256, 256>>>(adj);
    transpose_split_kernel<<<dim3(NN / 32, FOUT / 32, NH), dim3(32, 8)>>>();
    attn_mma_kernel<<<dim3(NN / 128, NH), 256, SM_TOTAL>>>(out);
}

// round 4
// speedup vs baseline: 2.1589x; 1.0237x over previous
#include <cuda_runtime.h>
#include <cuda_bf16.h>
#include <math.h>
#include <stdint.h>

#define NH   4
#define NN   4096
#define FIN  512
#define FOUT 128
#define LALPHA 0.2f
#define CH   64
#define NC   (NN / CH)

typedef unsigned long long u64;
typedef unsigned int u32;

// ---------------- scratch ----------------
__device__ float g_ham[NH * FIN * FOUT];
__device__ float g_A[NH * NN];
__device__ float g_Cv[NH * NN];
__device__ float g_fs[NH * NN];
__device__ float4 g_cp[NH * NN];                 // (fd, exp(fd), exp(0.2fd), 0)
__device__ u32 g_adjb[NN * (NN / 32)];
__device__ __nv_bfloat16 g_hTh[NH * FOUT * NN];  // [h][o][m] hi
__device__ __nv_bfloat16 g_hTl[NH * FOUT * NN];  // [h][o][m] lo

// ---------------- helpers ----------------
__device__ __forceinline__ u64 pack2(float lo, float hi) {
    u64 r; asm("mov.b64 %0, {%1, %2};" : "=l"(r) : "f"(lo), "f"(hi)); return r;
}
__device__ __forceinline__ void fma2(u64& d, u64 a, u64 b) {
    asm("fma.rn.f32x2 %0, %1, %2, %0;" : "+l"(d) : "l"(a), "l"(b));
}
__device__ __forceinline__ float2 unpack2(u64 v) {
    float lo, hi; asm("mov.b64 {%0, %1}, %2;" : "=f"(lo), "=f"(hi) : "l"(v));
    return make_float2(lo, hi);
}
__device__ __forceinline__ u32 smem_u32(const void* p) {
    u32 a; asm("{ .reg .u64 t; cvta.to.shared.u64 t, %1; cvt.u32.u64 %0, t; }" : "=r"(a) : "l"(p));
    return a;
}
#define SW128(x) ((x) ^ (((x) >> 3) & 0x70))

#define LDM4(d, addr) \
    asm volatile("ldmatrix.sync.aligned.m8n8.x4.shared.b16 {%0,%1,%2,%3}, [%4];" \
        : "=r"((d)[0]), "=r"((d)[1]), "=r"((d)[2]), "=r"((d)[3]) : "r"(addr))

#define MMA_BF16(c, a, b0, b1) \
    asm volatile("mma.sync.aligned.m16n8k16.row.col.f32.bf16.bf16.f32 " \
        "{%0,%1,%2,%3},{%4,%5,%6,%7},{%8,%9},{%0,%1,%2,%3};" \
        : "+f"((c)[0]), "+f"((c)[1]), "+f"((c)[2]), "+f"((c)[3]) \
        : "r"((a)[0]), "r"((a)[1]), "r"((a)[2]), "r"((a)[3]), "r"(b0), "r"(b1))

#define CPASYNC16(dst, src) \
    asm volatile("cp.async.cg.shared.global [%0], [%1], 16;" :: "r"(dst), "l"(src))

// ---------------- kernel 1: hamilton ----------------
__global__ void build_hamilton_kernel(const float* __restrict__ W) {
    int idx = blockIdx.x * blockDim.x + threadIdx.x;
    if (idx >= NH * FIN * FOUT) return;
    int o = idx & 127, f = (idx >> 7) & 511, h = idx >> 16;
    int q = f >> 7, fi = f & 127, p = o >> 5, oi = o & 31;
    const int negmask[4] = {0, 9, 3, 5};
    float sgn = ((negmask[q] >> p) & 1) ? -1.f : 1.f;
    g_ham[idx] = sgn * W[h * (128 * 128) + fi * 128 + (q ^ p) * 32 + oi];
}

// ---------------- kernel 2: h = x @ hamilton, fused epilogue ----------------
// Produces: g_hTh/g_hTl (transposed bf16 hi/lo), g_fs/g_A/g_Cv/g_cp. No g_h.
__global__ __launch_bounds__(128) void gemm_h_kernel(const float* __restrict__ x,
                                                     const float* __restrict__ a) {
    __shared__ float Xs[64][33];
    __shared__ float Hs[32][132];
    int t = threadIdx.x;
    int h = blockIdx.y, n0 = blockIdx.x * 64;
    int tx = t & 15, ty = t >> 4;
    u64 acc2[8][4];
#pragma unroll
    for (int i = 0; i < 8; i++)
#pragma unroll
        for (int j = 0; j < 4; j++) acc2[i][j] = 0ull;
    const float* hamb = g_ham + (size_t)h * (FIN * FOUT);

    for (int f0 = 0; f0 < FIN; f0 += 32) {
        __syncthreads();
#pragma unroll
        for (int i = 0; i < 16; i++) {
            int idx = t + i * 128;
            int r = idx >> 5, c = idx & 31;
            Xs[r][c] = x[(size_t)(n0 + r) * FIN + f0 + c];
        }
#pragma unroll
        for (int i = 0; i < 8; i++) {
            int idx4 = t + i * 128;
            int k = idx4 >> 5, c4 = idx4 & 31;
            *(float4*)&Hs[k][c4 * 4] = *(const float4*)(hamb + (size_t)(f0 + k) * FOUT + c4 * 4);
        }
        __syncthreads();
#pragma unroll
        for (int k = 0; k < 32; k++) {
            ulonglong2 q0 = *(const ulonglong2*)&Hs[k][tx * 8];
            ulonglong2 q1 = *(const ulonglong2*)&Hs[k][tx * 8 + 4];
            u64 bp[4] = {q0.x, q0.y, q1.x, q1.y};
#pragma unroll
            for (int i = 0; i < 8; i++) {
                float av = Xs[ty * 8 + i][k];
                u64 ap = pack2(av, av);
#pragma unroll
                for (int j = 0; j < 4; j++) fma2(acc2[i][j], ap, bp[j]);
            }
        }
    }

    // ---- epilogue ----
    // unpack: v[i][j] = h[n0+ty*8+i][tx*8+j]
    float v[8][8];
#pragma unroll
    for (int i = 0; i < 8; i++)
#pragma unroll
        for (int j = 0; j < 4; j++) {
            float2 pr = unpack2(acc2[i][j]);
            v[i][2 * j] = pr.x;
            v[i][2 * j + 1] = pr.y;
        }

    // (1) transposed bf16 hi/lo store: per col o = tx*8+j, rows n0+ty*8..+7
#pragma unroll
    for (int j = 0; j < 8; j++) {
        int o = tx * 8 + j;
        u32 hh[4], ll[4];
#pragma unroll
        for (int q = 0; q < 4; q++) {
            float f0 = v[2 * q][j], f1 = v[2 * q + 1][j];
            asm("cvt.rn.bf16x2.f32 %0, %1, %2;" : "=r"(hh[q]) : "f"(f1), "f"(f0));
            float l0 = f0 - __uint_as_float(hh[q] << 16);
            float l1 = f1 - __uint_as_float(hh[q] & 0xffff0000u);
            asm("cvt.rn.bf16x2.f32 %0, %1, %2;" : "=r"(ll[q]) : "f"(l1), "f"(l0));
        }
        size_t off = ((size_t)h * FOUT + o) * NN + n0 + ty * 8;
        *(uint4*)(g_hTh + off) = make_uint4(hh[0], hh[1], hh[2], hh[3]);
        *(uint4*)(g_hTl + off) = make_uint4(ll[0], ll[1], ll[2], ll[3]);
    }

    // (2) f_src/f_dst partial dots + 16-lane reduce
    float p1[8], p2[8];
    const float* ah = a + h * 256;
#pragma unroll
    for (int i = 0; i < 8; i++) { p1[i] = 0.f; p2[i] = 0.f; }
#pragma unroll
    for (int j = 0; j < 8; j++) {
        float asj = ah[tx * 8 + j];
        float adj_ = ah[128 + tx * 8 + j];
#pragma unroll
        for (int i = 0; i < 8; i++) {
            p1[i] += v[i][j] * asj;
            p2[i] += v[i][j] * adj_;
        }
    }
#pragma unroll
    for (int off = 8; off; off >>= 1) {
#pragma unroll
        for (int i = 0; i < 8; i++) {
            p1[i] += __shfl_xor_sync(0xffffffffu, p1[i], off);
            p2[i] += __shfl_xor_sync(0xffffffffu, p2[i], off);
        }
    }
    if (tx == 0) {
#pragma unroll
        for (int i = 0; i < 8; i++) {
            int idx = h * NN + n0 + ty * 8 + i;
            float s1 = p1[i], s2 = p2[i];
            g_fs[idx] = s1;
            g_A[idx]  = expf(s1);
            g_Cv[idx] = expf(LALPHA * s1);
            g_cp[idx] = make_float4(s2, expf(s2), expf(LALPHA * s2), 0.f);
        }
    }
}

// ---------------- kernel 3: pack adj bits (2 words/thread, MLP 16) ----------------
__global__ void pack_adj_kernel(const int* __restrict__ adj) {
    int idx = blockIdx.x * blockDim.x + threadIdx.x;   // word-pair index
    const int4* p = (const int4*)adj + (size_t)idx * 16;
    int4 vv[16];
#pragma unroll
    for (int i = 0; i < 16; i++) vv[i] = p[i];
    u32 w0 = 0, w1 = 0;
#pragma unroll
    for (int i = 0; i < 8; i++) {
        w0 |= ((u32)vv[i].x & 1u) << (4 * i);
        w0 |= ((u32)vv[i].y & 1u) << (4 * i + 1);
        w0 |= ((u32)vv[i].z & 1u) << (4 * i + 2);
        w0 |= ((u32)vv[i].w & 1u) << (4 * i + 3);
        w1 |= ((u32)vv[8 + i].x & 1u) << (4 * i);
        w1 |= ((u32)vv[8 + i].y & 1u) << (4 * i + 1);
        w1 |= ((u32)vv[8 + i].z & 1u) << (4 * i + 2);
        w1 |= ((u32)vv[8 + i].w & 1u) << (4 * i + 3);
    }
    *(uint2*)&g_adjb[2 * idx] = make_uint2(w0, w1);
}

// ---------------- kernel 4: HMMA attention ----------------
#define SM_RS    0
#define SM_PRM   512
#define SM_TILES 4096
#define STAGE_SZ 65536                   // Ph 16K | Pl 16K | Bh 16K | Bl 16K
#define SM_TOTAL (SM_TILES + 2 * STAGE_SZ)

__device__ __forceinline__ void build_P(char* Ph, char* Pl, const float4* prm,
                                        int r, int cb, u32 aw,
                                        float An, float Cn, float fsn, float& rsum) {
#pragma unroll
    for (int jj = 0; jj < 32; jj += 8) {
        u32 hp[4], lp[4];
#pragma unroll
        for (int q = 0; q < 4; q++) {
            float p[2];
#pragma unroll
            for (int e = 0; e < 2; e++) {
                int j = jj + q * 2 + e;
                float4 pr = prm[cb + j];
                float s1 = fsn + pr.x;
                float vv = (s1 > 0.f) ? (An * pr.y) : (Cn * pr.z);
                p[e] = ((aw >> j) & 1) ? vv : 0.f;
                rsum += p[e];
            }
            u32 hh;
            asm("cvt.rn.bf16x2.f32 %0, %1, %2;" : "=r"(hh) : "f"(p[1]), "f"(p[0]));
            hp[q] = hh;
            float l0 = p[0] - __uint_as_float(hh << 16);
            float l1 = p[1] - __uint_as_float(hh & 0xffff0000u);
            asm("cvt.rn.bf16x2.f32 %0, %1, %2;" : "=r"(lp[q]) : "f"(l1), "f"(l0));
        }
        u32 sw = SW128((u32)(r * 128 + (cb + jj) * 2));
        *(uint4*)(Ph + sw) = make_uint4(hp[0], hp[1], hp[2], hp[3]);
        *(uint4*)(Pl + sw) = make_uint4(lp[0], lp[1], lp[2], lp[3]);
    }
}

__global__ __launch_bounds__(256, 1) void attn_mma_kernel(float* __restrict__ out) {
    extern __shared__ char smem[];
    u32 sb = smem_u32(smem);
    float* rs = (float*)(smem + SM_RS);
    float4* prm_all = (float4*)(smem + SM_PRM);

    int t = threadIdx.x;
    int wid = t >> 5, L = t & 31;
    int h = blockIdx.y, n0 = blockIdx.x * 128, hN = h * NN;

    int r = t >> 1, chalf = t & 1, cb = chalf * 32;
    float An = g_A[hN + n0 + r], Cn = g_Cv[hN + n0 + r], fsn = g_fs[hN + n0 + r];
    const u32* adjrow = g_adjb + (size_t)(n0 + r) * (NN / 32) + chalf;
    float rsum = 0.f;

    int wr = wid & 3, wc = wid >> 2;
    float acc[2][8][4];
#pragma unroll
    for (int mt = 0; mt < 2; mt++)
#pragma unroll
        for (int n8 = 0; n8 < 8; n8++)
#pragma unroll
            for (int e = 0; e < 4; e++) acc[mt][n8][e] = 0.f;

    const __nv_bfloat16* hTh = g_hTh + (size_t)h * FOUT * NN;
    const __nv_bfloat16* hTl = g_hTl + (size_t)h * FOUT * NN;
    const float4* gcp = g_cp + hN;

    u32 xorx = (u32)((L & 7) << 4);

    // prologue: B(0) + params(0) + P(0)
    {
        u32 bh0 = sb + SM_TILES + 32768, bl0 = sb + SM_TILES + 49152;
#pragma unroll
        for (int i = 0; i < 4; i++) {
            int idx = t + i * 256;
            int o = idx >> 3, seg = idx & 7;
            u32 sw = SW128((u32)(o * 128 + seg * 16));
            CPASYNC16(bh0 + sw, hTh + (size_t)o * NN + seg * 8);
            CPASYNC16(bl0 + sw, hTl + (size_t)o * NN + seg * 8);
        }
        asm volatile("cp.async.commit_group;" ::: "memory");
        if (t < 64) prm_all[t] = gcp[t];
        __syncthreads();
        build_P(smem + SM_TILES, smem + SM_TILES + 16384, prm_all,
                r, cb, adjrow[0], An, Cn, fsn, rsum);
    }

    for (int c = 0; c < NC; c++) {
        int s = c & 1;
        int sn = s ^ 1;
        u32 stage  = sb + SM_TILES + s * STAGE_SZ;
        char* stgc = smem + SM_TILES + sn * STAGE_SZ;
        bool more = (c + 1 < NC);
        int m0n = (c + 1) * CH;

        __syncthreads();

        if (more) {
            u32 bhn = sb + SM_TILES + sn * STAGE_SZ + 32768;
            u32 bln = bhn + 16384;
#pragma unroll
            for (int i = 0; i < 4; i++) {
                int idx = t + i * 256;
                int o = idx >> 3, seg = idx & 7;
                u32 sw = SW128((u32)(o * 128 + seg * 16));
                CPASYNC16(bhn + sw, hTh + (size_t)o * NN + m0n + seg * 8);
                CPASYNC16(bln + sw, hTl + (size_t)o * NN + m0n + seg * 8);
            }
            asm volatile("cp.async.commit_group;" ::: "memory");
            if (t < 64) prm_all[sn * 64 + t] = gcp[m0n + t];
        }
        if (more) asm volatile("cp.async.wait_group 1;" ::: "memory");
        else      asm volatile("cp.async.wait_group 0;" ::: "memory");
        __syncthreads();

        // MMA over stage s, ILP-friendly order (reuse distance 4 per acc)
        {
            u32 aPh = stage, aPl = stage + 16384;
            u32 bBh = stage + 32768, bBl = stage + 49152;
            u32 aRow = (u32)((wr * 32 + (L & 15)) * 128);
            u32 aHalf = (u32)((L >> 4) * 16);
            u32 bRow = (u32)((wc * 64 + ((L >> 4) & 1) * 8 + (L & 7)) * 128);
            u32 bHalf = (u32)(((L >> 3) & 1) * 16);
#pragma unroll
            for (int kt = 0; kt < 4; kt++) {
                u32 aCol = ((u32)(kt * 32) + aHalf) ^ xorx;
                u32 bCol = ((u32)(kt * 32) + bHalf) ^ xorx;
                u32 ah[2][4], al[2][4];
#pragma unroll
                for (int mt = 0; mt < 2; mt++) {
                    u32 ra = aRow + (u32)(mt * 2048) + aCol;
                    LDM4(ah[mt], aPh + ra);
                    LDM4(al[mt], aPl + ra);
                }
#pragma unroll
                for (int ng = 0; ng < 4; ng++) {
                    u32 rb = bRow + (u32)(ng * 2048) + bCol;
                    u32 bh[4], bl[4];
                    LDM4(bh, bBh + rb);
                    LDM4(bl, bBl + rb);
#pragma unroll
                    for (int term = 0; term < 3; term++) {
#pragma unroll
                        for (int e = 0; e < 2; e++) {
#pragma unroll
                            for (int mt = 0; mt < 2; mt++) {
                                const u32* aa = (term == 2) ? al[mt] : ah[mt];
                                u32 b0 = (term == 1) ? bl[2 * e] : bh[2 * e];
                                u32 b1 = (term == 1) ? bl[2 * e + 1] : bh[2 * e + 1];
                                MMA_BF16(acc[mt][2 * ng + e], aa, b0, b1);
                            }
                        }
                    }
                }
            }
        }

        if (more)
            build_P(stgc, stgc + 16384, prm_all + sn * 64,
                    r, cb, adjrow[m0n >> 5], An, Cn, fsn, rsum);
    }

    rsum += __shfl_xor_sync(0xffffffffu, rsum, 1);
    if ((t & 1) == 0) rs[r] = rsum;
    __syncthreads();

    int gid = L >> 2, tid = L & 3;
#pragma unroll
    for (int mt = 0; mt < 2; mt++) {
#pragma unroll
        for (int half = 0; half < 2; half++) {
            int rt = wr * 32 + mt * 16 + half * 8 + gid;
            float inv = 1.f / rs[rt];
            float* op = out + (size_t)(n0 + rt) * (NH * FOUT) + h * FOUT + wc * 64 + tid * 2;
#pragma unroll
            for (int n8 = 0; n8 < 8; n8++) {
                float v0 = acc[mt][n8][half * 2] * inv;
                float v1 = acc[mt][n8][half * 2 + 1] * inv;
                v0 = (v0 > 0.f) ? v0 : expm1f(v0);
                v1 = (v1 > 0.f) ? v1 : expm1f(v1);
                *(float2*)(op + n8 * 8) = make_float2(v0, v1);
            }
        }
    }
}

// ---------------- launch ----------------
extern "C" void kernel_launch(void* const* d_in, const int* in_sizes, int n_in,
                              void* d_out, int out_size) {
    const float* x  = (const float*)d_in[0];
    const int* adj  = (const int*)d_in[1];
    const float* W  = (const float*)d_in[2];
    const float* a  = (const float*)d_in[3];
    float* out = (float*)d_out;

    cudaFuncSetAttribute(attn_mma_kernel, cudaFuncAttributeMaxDynamicSharedMemorySize, SM_TOTAL);

    build_hamilton_kernel<<<(NH * FIN * FOUT + 255) / 256, 256>>>(W);
    gemm_h_kernel<<<dim3(NN / 64, NH), 128>>>(x, a);
    pack_adj_kernel<<<(NN * (NN / 64)) / 256, 256>>>(adj);
    attn_mma_kernel<<<dim3(NN / 128, NH), 256, SM_TOTAL>>>(out);
}

// round 5
// speedup vs baseline: 2.6909x; 1.2464x over previous
#include <cuda_runtime.h>
#include <cuda_bf16.h>
#include <math.h>
#include <stdint.h>

#define NH   4
#define NN   4096
#define FIN  512
#define FOUT 128
#define LALPHA 0.2f
#define CH   64
#define NC   (NN / CH)

typedef unsigned long long u64;
typedef unsigned int u32;

// ---------------- scratch ----------------
__device__ float g_ham[NH * FIN * FOUT];
__device__ float g_A[NH * NN];
__device__ float g_Cv[NH * NN];
__device__ float g_fs[NH * NN];
__device__ float4 g_cp[NH * NN];                 // (fd, exp(fd), exp(0.2fd), 0)
__device__ u32 g_adjb[NN * (NN / 32)];
__device__ __nv_bfloat16 g_hTh[NH * FOUT * NN];  // [h][o][m] hi
__device__ __nv_bfloat16 g_hTl[NH * FOUT * NN];  // [h][o][m] lo

// ---------------- helpers ----------------
__device__ __forceinline__ u64 pack2(float lo, float hi) {
    u64 r; asm("mov.b64 %0, {%1, %2};" : "=l"(r) : "f"(lo), "f"(hi)); return r;
}
__device__ __forceinline__ void fma2(u64& d, u64 a, u64 b) {
    asm("fma.rn.f32x2 %0, %1, %2, %0;" : "+l"(d) : "l"(a), "l"(b));
}
__device__ __forceinline__ float2 unpack2(u64 v) {
    float lo, hi; asm("mov.b64 {%0, %1}, %2;" : "=f"(lo), "=f"(hi) : "l"(v));
    return make_float2(lo, hi);
}
__device__ __forceinline__ u32 smem_u32(const void* p) {
    u32 a; asm("{ .reg .u64 t; cvta.to.shared.u64 t, %1; cvt.u32.u64 %0, t; }" : "=r"(a) : "l"(p));
    return a;
}
#define SW128(x) ((x) ^ (((x) >> 3) & 0x70))

#define LDM4(d, addr) \
    asm volatile("ldmatrix.sync.aligned.m8n8.x4.shared.b16 {%0,%1,%2,%3}, [%4];" \
        : "=r"((d)[0]), "=r"((d)[1]), "=r"((d)[2]), "=r"((d)[3]) : "r"(addr))

#define MMA_BF16(c, a, b0, b1) \
    asm volatile("mma.sync.aligned.m16n8k16.row.col.f32.bf16.bf16.f32 " \
        "{%0,%1,%2,%3},{%4,%5,%6,%7},{%8,%9},{%0,%1,%2,%3};" \
        : "+f"((c)[0]), "+f"((c)[1]), "+f"((c)[2]), "+f"((c)[3]) \
        : "r"((a)[0]), "r"((a)[1]), "r"((a)[2]), "r"((a)[3]), "r"(b0), "r"(b1))

#define CPASYNC16(dst, src) \
    asm volatile("cp.async.cg.shared.global [%0], [%1], 16;" :: "r"(dst), "l"(src))

#define BAR_SYNC(id, cnt)   asm volatile("bar.sync %0, %1;" :: "r"(id), "r"(cnt) : "memory")
#define BAR_ARRIVE(id, cnt) asm volatile("bar.arrive %0, %1;" :: "r"(id), "r"(cnt) : "memory")

// ---------------- kernel 1: hamilton ----------------
__global__ void build_hamilton_kernel(const float* __restrict__ W) {
    int idx = blockIdx.x * blockDim.x + threadIdx.x;
    if (idx >= NH * FIN * FOUT) return;
    int o = idx & 127, f = (idx >> 7) & 511, h = idx >> 16;
    int q = f >> 7, fi = f & 127, p = o >> 5, oi = o & 31;
    const int negmask[4] = {0, 9, 3, 5};
    float sgn = ((negmask[q] >> p) & 1) ? -1.f : 1.f;
    g_ham[idx] = sgn * W[h * (128 * 128) + fi * 128 + (q ^ p) * 32 + oi];
}

// ---------------- kernel 2: h = x @ hamilton, fused epilogue ----------------
__global__ __launch_bounds__(128) void gemm_h_kernel(const float* __restrict__ x,
                                                     const float* __restrict__ a) {
    __shared__ float Xs[64][33];
    __shared__ float Hs[32][132];
    int t = threadIdx.x;
    int h = blockIdx.y, n0 = blockIdx.x * 64;
    int tx = t & 15, ty = t >> 4;
    u64 acc2[8][4];
#pragma unroll
    for (int i = 0; i < 8; i++)
#pragma unroll
        for (int j = 0; j < 4; j++) acc2[i][j] = 0ull;
    const float* hamb = g_ham + (size_t)h * (FIN * FOUT);

    for (int f0 = 0; f0 < FIN; f0 += 32) {
        __syncthreads();
#pragma unroll
        for (int i = 0; i < 16; i++) {
            int idx = t + i * 128;
            int r = idx >> 5, c = idx & 31;
            Xs[r][c] = x[(size_t)(n0 + r) * FIN + f0 + c];
        }
#pragma unroll
        for (int i = 0; i < 8; i++) {
            int idx4 = t + i * 128;
            int k = idx4 >> 5, c4 = idx4 & 31;
            *(float4*)&Hs[k][c4 * 4] = *(const float4*)(hamb + (size_t)(f0 + k) * FOUT + c4 * 4);
        }
        __syncthreads();
#pragma unroll
        for (int k = 0; k < 32; k++) {
            ulonglong2 q0 = *(const ulonglong2*)&Hs[k][tx * 8];
            ulonglong2 q1 = *(const ulonglong2*)&Hs[k][tx * 8 + 4];
            u64 bp[4] = {q0.x, q0.y, q1.x, q1.y};
#pragma unroll
            for (int i = 0; i < 8; i++) {
                float av = Xs[ty * 8 + i][k];
                u64 ap = pack2(av, av);
#pragma unroll
                for (int j = 0; j < 4; j++) fma2(acc2[i][j], ap, bp[j]);
            }
        }
    }

    float v[8][8];
#pragma unroll
    for (int i = 0; i < 8; i++)
#pragma unroll
        for (int j = 0; j < 4; j++) {
            float2 pr = unpack2(acc2[i][j]);
            v[i][2 * j] = pr.x;
            v[i][2 * j + 1] = pr.y;
        }

#pragma unroll
    for (int j = 0; j < 8; j++) {
        int o = tx * 8 + j;
        u32 hh[4], ll[4];
#pragma unroll
        for (int q = 0; q < 4; q++) {
            float f0 = v[2 * q][j], f1 = v[2 * q + 1][j];
            asm("cvt.rn.bf16x2.f32 %0, %1, %2;" : "=r"(hh[q]) : "f"(f1), "f"(f0));
            float l0 = f0 - __uint_as_float(hh[q] << 16);
            float l1 = f1 - __uint_as_float(hh[q] & 0xffff0000u);
            asm("cvt.rn.bf16x2.f32 %0, %1, %2;" : "=r"(ll[q]) : "f"(l1), "f"(l0));
        }
        size_t off = ((size_t)h * FOUT + o) * NN + n0 + ty * 8;
        *(uint4*)(g_hTh + off) = make_uint4(hh[0], hh[1], hh[2], hh[3]);
        *(uint4*)(g_hTl + off) = make_uint4(ll[0], ll[1], ll[2], ll[3]);
    }

    float p1[8], p2[8];
    const float* ah = a + h * 256;
#pragma unroll
    for (int i = 0; i < 8; i++) { p1[i] = 0.f; p2[i] = 0.f; }
#pragma unroll
    for (int j = 0; j < 8; j++) {
        float asj = ah[tx * 8 + j];
        float adj_ = ah[128 + tx * 8 + j];
#pragma unroll
        for (int i = 0; i < 8; i++) {
            p1[i] += v[i][j] * asj;
            p2[i] += v[i][j] * adj_;
        }
    }
#pragma unroll
    for (int off = 8; off; off >>= 1) {
#pragma unroll
        for (int i = 0; i < 8; i++) {
            p1[i] += __shfl_xor_sync(0xffffffffu, p1[i], off);
            p2[i] += __shfl_xor_sync(0xffffffffu, p2[i], off);
        }
    }
    if (tx == 0) {
#pragma unroll
        for (int i = 0; i < 8; i++) {
            int idx = h * NN + n0 + ty * 8 + i;
            float s1 = p1[i], s2 = p2[i];
            g_fs[idx] = s1;
            g_A[idx]  = expf(s1);
            g_Cv[idx] = expf(LALPHA * s1);
            g_cp[idx] = make_float4(s2, expf(s2), expf(LALPHA * s2), 0.f);
        }
    }
}

// ---------------- kernel 3: pack adj bits ----------------
__global__ void pack_adj_kernel(const int* __restrict__ adj) {
    int idx = blockIdx.x * blockDim.x + threadIdx.x;
    const int4* p = (const int4*)adj + (size_t)idx * 16;
    int4 vv[16];
#pragma unroll
    for (int i = 0; i < 16; i++) vv[i] = p[i];
    u32 w0 = 0, w1 = 0;
#pragma unroll
    for (int i = 0; i < 8; i++) {
        w0 |= ((u32)vv[i].x & 1u) << (4 * i);
        w0 |= ((u32)vv[i].y & 1u) << (4 * i + 1);
        w0 |= ((u32)vv[i].z & 1u) << (4 * i + 2);
        w0 |= ((u32)vv[i].w & 1u) << (4 * i + 3);
        w1 |= ((u32)vv[8 + i].x & 1u) << (4 * i);
        w1 |= ((u32)vv[8 + i].y & 1u) << (4 * i + 1);
        w1 |= ((u32)vv[8 + i].z & 1u) << (4 * i + 2);
        w1 |= ((u32)vv[8 + i].w & 1u) << (4 * i + 3);
    }
    *(uint2*)&g_adjb[2 * idx] = make_uint2(w0, w1);
}

// ---------------- kernel 4: warp-specialized HMMA attention ----------------
// 384 threads: warps 0-7 consumers (MMA), warps 8-11 producers (P build + B loads).
#define SM_RS    0                        // 128 floats
#define SM_PRM   512                      // 2 stages * 64 float4
#define SM_TILES 4096
#define STAGE_SZ 65536                    // Ph 16K | Pl 16K | Bh 16K | Bl 16K
#define SM_TOTAL (SM_TILES + 2 * STAGE_SZ)

// named barrier ids
#define BFULL0 1
#define BFULL1 2
#define BEMPT0 3
#define BEMPT1 4
#define BPROD  5

__global__ __launch_bounds__(384, 1) void attn_mma_kernel(float* __restrict__ out) {
    extern __shared__ char smem[];
    u32 sb = smem_u32(smem);
    float* rs = (float*)(smem + SM_RS);
    float4* prm_all = (float4*)(smem + SM_PRM);

    int t = threadIdx.x;
    int h = blockIdx.y, n0 = blockIdx.x * 128, hN = h * NN;

    if (t < 256) {
        // ================= CONSUMERS =================
        int wid = t >> 5, L = t & 31;
        int wr = wid & 3, wc = wid >> 2;
        float acc[2][8][4];
#pragma unroll
        for (int mt = 0; mt < 2; mt++)
#pragma unroll
            for (int n8 = 0; n8 < 8; n8++)
#pragma unroll
                for (int e = 0; e < 4; e++) acc[mt][n8][e] = 0.f;

        u32 xorx = (u32)((L & 7) << 4);
        u32 aRow = (u32)((wr * 32 + (L & 15)) * 128);
        u32 aHalf = (u32)((L >> 4) * 16);
        u32 bRow = (u32)((wc * 64 + ((L >> 4) & 1) * 8 + (L & 7)) * 128);
        u32 bHalf = (u32)(((L >> 3) & 1) * 16);

        for (int c = 0; c < NC; c++) {
            int s = c & 1;
            BAR_SYNC(s ? BFULL1 : BFULL0, 384);
            u32 stage = sb + SM_TILES + s * STAGE_SZ;
            u32 aPh = stage, aPl = stage + 16384;
            u32 bBh = stage + 32768, bBl = stage + 49152;
#pragma unroll
            for (int kt = 0; kt < 4; kt++) {
                u32 aCol = ((u32)(kt * 32) + aHalf) ^ xorx;
                u32 bCol = ((u32)(kt * 32) + bHalf) ^ xorx;
                u32 ah[2][4], al[2][4];
#pragma unroll
                for (int mt = 0; mt < 2; mt++) {
                    u32 ra = aRow + (u32)(mt * 2048) + aCol;
                    LDM4(ah[mt], aPh + ra);
                    LDM4(al[mt], aPl + ra);
                }
#pragma unroll
                for (int ng = 0; ng < 4; ng++) {
                    u32 rb = bRow + (u32)(ng * 2048) + bCol;
                    u32 bh[4], bl[4];
                    LDM4(bh, bBh + rb);
                    LDM4(bl, bBl + rb);
#pragma unroll
                    for (int term = 0; term < 3; term++) {
#pragma unroll
                        for (int e = 0; e < 2; e++) {
#pragma unroll
                            for (int mt = 0; mt < 2; mt++) {
                                const u32* aa = (term == 2) ? al[mt] : ah[mt];
                                u32 b0 = (term == 1) ? bl[2 * e] : bh[2 * e];
                                u32 b1 = (term == 1) ? bl[2 * e + 1] : bh[2 * e + 1];
                                MMA_BF16(acc[mt][2 * ng + e], aa, b0, b1);
                            }
                        }
                    }
                }
            }
            BAR_ARRIVE(s ? BEMPT1 : BEMPT0, 384);
        }

        __syncthreads();   // rs[] ready (producers wrote after their loop)

        int gid = L >> 2, tid = L & 3;
#pragma unroll
        for (int mt = 0; mt < 2; mt++) {
#pragma unroll
            for (int half = 0; half < 2; half++) {
                int rt = wr * 32 + mt * 16 + half * 8 + gid;
                float inv = 1.f / rs[rt];
                float* op = out + (size_t)(n0 + rt) * (NH * FOUT) + h * FOUT + wc * 64 + tid * 2;
#pragma unroll
                for (int n8 = 0; n8 < 8; n8++) {
                    float v0 = acc[mt][n8][half * 2] * inv;
                    float v1 = acc[mt][n8][half * 2 + 1] * inv;
                    v0 = (v0 > 0.f) ? v0 : expm1f(v0);
                    v1 = (v1 > 0.f) ? v1 : expm1f(v1);
                    *(float2*)(op + n8 * 8) = make_float2(v0, v1);
                }
            }
        }
    } else {
        // ================= PRODUCERS =================
        int pt = t - 256;            // 0..127
        int pr = pt >> 1, ch = pt & 1;
        int r0 = 2 * pr, r1 = 2 * pr + 1;
        int cb = ch * 32;
        float An0 = g_A[hN + n0 + r0], Cn0 = g_Cv[hN + n0 + r0], fs0 = g_fs[hN + n0 + r0];
        float An1 = g_A[hN + n0 + r1], Cn1 = g_Cv[hN + n0 + r1], fs1 = g_fs[hN + n0 + r1];
        const u32* aj0 = g_adjb + (size_t)(n0 + r0) * (NN / 32) + ch;
        const u32* aj1 = g_adjb + (size_t)(n0 + r1) * (NN / 32) + ch;
        float rsum0 = 0.f, rsum1 = 0.f;
        const __nv_bfloat16* hTh = g_hTh + (size_t)h * FOUT * NN;
        const __nv_bfloat16* hTl = g_hTl + (size_t)h * FOUT * NN;
        const float4* gcp = g_cp + hN;

        for (int c = 0; c < NC; c++) {
            int s = c & 1;
            int m0 = c * CH;
            if (c >= 2) BAR_SYNC(s ? BEMPT1 : BEMPT0, 384);

            // B tile loads (hi + lo): 16 cp.async per thread
            u32 bhb = sb + SM_TILES + s * STAGE_SZ + 32768;
            u32 blb = bhb + 16384;
#pragma unroll
            for (int i = 0; i < 8; i++) {
                int idx = pt + i * 128;
                int o = idx >> 3, seg = idx & 7;
                u32 sw = SW128((u32)(o * 128 + seg * 16));
                CPASYNC16(bhb + sw, hTh + (size_t)o * NN + m0 + seg * 8);
                CPASYNC16(blb + sw, hTl + (size_t)o * NN + m0 + seg * 8);
            }
            asm volatile("cp.async.commit_group;" ::: "memory");

            // params staging
            if (pt < 64) prm_all[s * 64 + pt] = gcp[m0 + pt];
            BAR_SYNC(BPROD, 128);

            // build P (2 rows x 32 cols)
            const float4* prm = prm_all + s * 64;
            char* Ph = smem + SM_TILES + s * STAGE_SZ;
            char* Pl = Ph + 16384;
            u32 aw0 = aj0[2 * c], aw1 = aj1[2 * c];
#pragma unroll
            for (int rr = 0; rr < 2; rr++) {
                int r = rr ? r1 : r0;
                float An = rr ? An1 : An0, Cn = rr ? Cn1 : Cn0, fsn = rr ? fs1 : fs0;
                u32 aw = rr ? aw1 : aw0;
                float rl = 0.f;
#pragma unroll
                for (int jj = 0; jj < 32; jj += 8) {
                    u32 hp[4], lp[4];
#pragma unroll
                    for (int q = 0; q < 4; q++) {
                        float p[2];
#pragma unroll
                        for (int e = 0; e < 2; e++) {
                            int j = jj + q * 2 + e;
                            float4 prv = prm[cb + j];
                            float s1 = fsn + prv.x;
                            float vv = (s1 > 0.f) ? (An * prv.y) : (Cn * prv.z);
                            p[e] = ((aw >> j) & 1) ? vv : 0.f;
                            rl += p[e];
                        }
                        u32 hh;
                        asm("cvt.rn.bf16x2.f32 %0, %1, %2;" : "=r"(hh) : "f"(p[1]), "f"(p[0]));
                        hp[q] = hh;
                        float l0 = p[0] - __uint_as_float(hh << 16);
                        float l1 = p[1] - __uint_as_float(hh & 0xffff0000u);
                        asm("cvt.rn.bf16x2.f32 %0, %1, %2;" : "=r"(lp[q]) : "f"(l1), "f"(l0));
                    }
                    u32 sw = SW128((u32)(r * 128 + (cb + jj) * 2));
                    *(uint4*)(Ph + sw) = make_uint4(hp[0], hp[1], hp[2], hp[3]);
                    *(uint4*)(Pl + sw) = make_uint4(lp[0], lp[1], lp[2], lp[3]);
                }
                if (rr) rsum1 += rl; else rsum0 += rl;
            }

            asm volatile("cp.async.wait_group 0;" ::: "memory");
            BAR_ARRIVE(s ? BFULL1 : BFULL0, 384);
        }

        // combine row-sum halves (pt even/odd adjacent lanes)
        rsum0 += __shfl_xor_sync(0xffffffffu, rsum0, 1);
        rsum1 += __shfl_xor_sync(0xffffffffu, rsum1, 1);
        if (ch == 0) { rs[r0] = rsum0; rs[r1] = rsum1; }
        __syncthreads();
    }
}

// ---------------- launch ----------------
extern "C" void kernel_launch(void* const* d_in, const int* in_sizes, int n_in,
                              void* d_out, int out_size) {
    const float* x  = (const float*)d_in[0];
    const int* adj  = (const int*)d_in[1];
    const float* W  = (const float*)d_in[2];
    const float* a  = (const float*)d_in[3];
    float* out = (float*)d_out;

    cudaFuncSetAttribute(attn_mma_kernel, cudaFuncAttributeMaxDynamicSharedMemorySize, SM_TOTAL);

    build_hamilton_kernel<<<(NH * FIN * FOUT + 255) / 256, 256>>>(W);
    gemm_h_kernel<<<dim3(NN / 64, NH), 128>>>(x, a);
    pack_adj_kernel<<<(NN * (NN / 64)) / 256, 256>>>(adj);
    attn_mma_kernel<<<dim3(NN / 128, NH), 384, SM_TOTAL>>>(out);
}